// round 8
// baseline (speedup 1.0000x reference)
#include <cuda_runtime.h>
#include <cuda_bf16.h>
#include <cstdint>

#define HDIM 1024
#define BDIM 2048
#define SDIM 64
#define MROWS (BDIM * SDIM)   // 131072

// ---------------- scratch ----------------
__device__ __nv_bfloat16 g_wqt [(size_t)HDIM * HDIM];    // Wq^T bf16 (n-major)
__device__ __nv_bfloat16 g_wkt [(size_t)HDIM * HDIM];    // Wk^T bf16
__device__ __nv_bfloat16 g_kc  [(size_t)MROWS * HDIM];   // prev_out_M @ Wk
__device__ __nv_bfloat16 g_qpre[(size_t)BDIM * HDIM];    // in_val @ Wq
__device__ float         g_q   [(size_t)BDIM * HDIM];    // LN(query)
__device__ float         g_beta[(size_t)BDIM * SDIM];

#define CPASYNC16(sm, gm) \
    asm volatile("cp.async.cg.shared.global [%0], [%1], 16;\n" :: "r"(sm), "l"(gm))
#define CP_COMMIT() asm volatile("cp.async.commit_group;\n" ::: "memory")
#define CP_WAITN(n) asm volatile("cp.async.wait_group %0;\n" :: "n"(n) : "memory")
#define LDMX4(r0, r1, r2, r3, a) \
    asm volatile("ldmatrix.sync.aligned.m8n8.x4.shared.b16 {%0,%1,%2,%3}, [%4];" \
        : "=r"(r0), "=r"(r1), "=r"(r2), "=r"(r3) : "r"(a))

__device__ __forceinline__ uint32_t smem_u32(const void* p) {
    uint32_t a;
    asm("{ .reg .u64 t; cvta.to.shared.u64 t, %1; cvt.u32.u64 %0, t; }" : "=r"(a) : "l"(p));
    return a;
}

// ================= pipelined bf16 mma.sync GEMM, fused A-convert =================
// C[M,1024] = bf16(A_fp32[M,1024]) @ Bt^T  (Bt n-major bf16).
// CTA tile 128x128, k-chunk 32, 4-stage ring, 2 CTAs/SM, 8 warps (2x4), warp 64x32.
// A: LDG fp32 (pipelined regs) -> cvt -> STS bf16.  B: cp.async bf16.
#define NSTG   4
#define KC     32
#define CHUNKS (HDIM / KC)              // 32
#define RSTRIDE 80                      // bytes/row: 32 bf16 (64B) + 16B pad
#define STG_A   (128 * RSTRIDE)         // 10240 B
#define STG_BYTES (2 * STG_A)           // 20480 B
#define GEMM_SMEM (NSTG * STG_BYTES)    // 81920 B

__global__ __launch_bounds__(256, 2) void gemm_bf16_k(
    const float* __restrict__ A, const __nv_bfloat16* __restrict__ Bt,
    __nv_bfloat16* __restrict__ C)
{
    extern __shared__ __align__(128) char smem[];
    const uint32_t sb = smem_u32(smem);

    const int tid   = threadIdx.x;
    const int lane  = tid & 31;
    const int wid   = tid >> 5;
    const int warpM = wid >> 2;
    const int warpN = wid & 3;
    const size_t bm = (size_t)blockIdx.y * 128;
    const size_t bn = (size_t)blockIdx.x * 128;

    float acc[4][4][4];
    #pragma unroll
    for (int mt = 0; mt < 4; mt++)
        #pragma unroll
        for (int nt = 0; nt < 4; nt++)
            #pragma unroll
            for (int i = 0; i < 4; i++) acc[mt][nt][i] = 0.f;

    // A producer: row = tid>>1, 16 fp32 at col (tid&1)*16
    const int arow = tid >> 1;
    const int ac0  = (tid & 1) * 16;
    const float* gA = A + (bm + arow) * HDIM + ac0;
    const uint32_t aDst = arow * RSTRIDE + ac0 * 2;   // bf16 bytes

    // B producer: row = tid>>1, 2x16B at granule (tid&1)*2
    const int brow = tid >> 1;
    const int bg   = (tid & 1) * 2;
    const __nv_bfloat16* gB = Bt + (bn + brow) * HDIM + bg * 8;
    const uint32_t bDst = STG_A + brow * RSTRIDE + bg * 16;

    // ldmatrix offsets
    const uint32_t aF = (warpM * 64 + ((lane >> 3) & 1) * 8 + (lane & 7)) * RSTRIDE
                      + (lane >> 4) * 16;
    const uint32_t bF = STG_A
                      + (warpN * 32 + ((lane >> 4) & 1) * 8 + (lane & 7)) * RSTRIDE
                      + ((lane >> 3) & 1) * 16;

    float4 abuf[4];

    // ---- helpers as lambdas ----
    auto ldgA = [&](int kt) {
        const float* src = gA + kt * KC;
        abuf[0] = *(const float4*)(src);
        abuf[1] = *(const float4*)(src + 4);
        abuf[2] = *(const float4*)(src + 8);
        abuf[3] = *(const float4*)(src + 12);
    };
    auto stsA = [&](int slot) {
        __nv_bfloat162 h[8];
        #pragma unroll
        for (int i = 0; i < 4; i++) {
            h[2*i]   = __floats2bfloat162_rn(abuf[i].x, abuf[i].y);
            h[2*i+1] = __floats2bfloat162_rn(abuf[i].z, abuf[i].w);
        }
        uint4* d = (uint4*)(smem + slot * STG_BYTES + aDst);
        d[0] = ((uint4*)h)[0];
        d[1] = ((uint4*)h)[1];
    };
    auto cpB = [&](int kt, int slot) {
        const __nv_bfloat16* src = gB + kt * KC;
        const uint32_t d = sb + slot * STG_BYTES + bDst;
        CPASYNC16(d,      src);
        CPASYNC16(d + 16, src + 8);
        CP_COMMIT();
    };

    // ---- prologue: chunks 0..2 staged, chunk 3 in regs ----
    #pragma unroll
    for (int p = 0; p < 3; p++) {
        ldgA(p);
        stsA(p);
        cpB(p, p);
    }
    ldgA(3);

    for (int kt = 0; kt < CHUNKS; kt++) {
        if      (kt < CHUNKS - 2) CP_WAITN(2);
        else if (kt < CHUNKS - 1) CP_WAITN(1);
        else                      CP_WAITN(0);
        __syncthreads();   // chunk kt visible; slot (kt+3)%4 free

        if (kt + 3 < CHUNKS) {
            const int slot = (kt + 3) % NSTG;
            stsA(slot);               // regs hold chunk kt+3
            cpB(kt + 3, slot);
            if (kt + 4 < CHUNKS) ldgA(kt + 4);
        }

        const uint32_t stg = sb + (kt % NSTG) * STG_BYTES;
        #pragma unroll
        for (int ks = 0; ks < KC; ks += 16) {
            uint32_t af[4][4];
            uint32_t bf[4][2];
            #pragma unroll
            for (int mt = 0; mt < 4; mt++)
                LDMX4(af[mt][0], af[mt][1], af[mt][2], af[mt][3],
                      stg + aF + mt * 16 * RSTRIDE + ks * 2);
            #pragma unroll
            for (int np = 0; np < 2; np++) {
                uint32_t b0, b1, b2, b3;
                LDMX4(b0, b1, b2, b3, stg + bF + np * 16 * RSTRIDE + ks * 2);
                bf[2*np][0]   = b0; bf[2*np][1]   = b1;
                bf[2*np+1][0] = b2; bf[2*np+1][1] = b3;
            }
            #pragma unroll
            for (int mt = 0; mt < 4; mt++)
                #pragma unroll
                for (int nt = 0; nt < 4; nt++)
                    asm volatile(
                        "mma.sync.aligned.m16n8k16.row.col.f32.bf16.bf16.f32 "
                        "{%0,%1,%2,%3},{%4,%5,%6,%7},{%8,%9},{%0,%1,%2,%3};\n"
                        : "+f"(acc[mt][nt][0]), "+f"(acc[mt][nt][1]),
                          "+f"(acc[mt][nt][2]), "+f"(acc[mt][nt][3])
                        : "r"(af[mt][0]), "r"(af[mt][1]), "r"(af[mt][2]), "r"(af[mt][3]),
                          "r"(bf[nt][0]), "r"(bf[nt][1]));
        }
    }

    #pragma unroll
    for (int mt = 0; mt < 4; mt++) {
        int r = warpM * 64 + mt * 16 + (lane >> 2);
        #pragma unroll
        for (int nt = 0; nt < 4; nt++) {
            size_t c  = bn + warpN * 32 + nt * 8 + (lane & 3) * 2;
            size_t b0 = (bm + r) * HDIM + c;
            *(__nv_bfloat162*)(C + b0) =
                __floats2bfloat162_rn(acc[mt][nt][0], acc[mt][nt][1]);
            *(__nv_bfloat162*)(C + b0 + (size_t)8 * HDIM) =
                __floats2bfloat162_rn(acc[mt][nt][2], acc[mt][nt][3]);
        }
    }
}

// ---------------- transpose + convert: Wt[n][k] = bf16(W[k][n]) ----------------
__global__ __launch_bounds__(256) void cvtT_k(const float* __restrict__ W,
                                              __nv_bfloat16* __restrict__ Wt)
{
    __shared__ float t[32][33];
    int x  = blockIdx.x * 32 + threadIdx.x;
    int y0 = blockIdx.y * 32;
    #pragma unroll
    for (int r = threadIdx.y; r < 32; r += 8)
        t[r][threadIdx.x] = W[(size_t)(y0 + r) * HDIM + x];
    __syncthreads();
    int xo = y0 + threadIdx.x;
    #pragma unroll
    for (int r = threadIdx.y; r < 32; r += 8)
        Wt[(size_t)(blockIdx.x * 32 + r) * HDIM + xo] = __float2bfloat16(t[threadIdx.x][r]);
}

// ---------------- LayerNorm for query ----------------
__global__ __launch_bounds__(256) void ln_q_k(
    const __nv_bfloat16* __restrict__ qpre,
    const float* __restrict__ bq, const float* __restrict__ gq,
    const float* __restrict__ betaq, float* __restrict__ qout)
{
    const int lane = threadIdx.x & 31;
    const int wid  = threadIdx.x >> 5;
    const int row  = blockIdx.x * 8 + wid;
    const size_t base = (size_t)row * HDIM;

    float x[32];
    float s = 0.f, sq = 0.f;
    #pragma unroll
    for (int i = 0; i < 16; i++) {
        int j = i * 64 + lane * 2;
        __nv_bfloat162 v = *(const __nv_bfloat162*)(qpre + base + j);
        float a = __low2float(v)  + bq[j];
        float c = __high2float(v) + bq[j + 1];
        x[2*i] = a; x[2*i+1] = c;
        s += a + c; sq += a * a + c * c;
    }
    #pragma unroll
    for (int o = 16; o > 0; o >>= 1) {
        s  += __shfl_xor_sync(0xffffffffu, s,  o);
        sq += __shfl_xor_sync(0xffffffffu, sq, o);
    }
    float mean = s * (1.f / 1024.f);
    float var  = sq * (1.f / 1024.f) - mean * mean;
    float rstd = rsqrtf(var + 1e-5f);
    #pragma unroll
    for (int i = 0; i < 16; i++) {
        int j = i * 64 + lane * 2;
        float2 o;
        o.x = (x[2*i]   - mean) * rstd * gq[j]   + betaq[j];
        o.y = (x[2*i+1] - mean) * rstd * gq[j+1] + betaq[j+1];
        *(float2*)(qout + base + j) = o;
    }
}

// ---------------- fused: keyp-LN + relu(q+keyp) . Wb -> beta ----------------
__global__ __launch_bounds__(256) void beta_k(
    const __nv_bfloat16* __restrict__ kc, const float* __restrict__ q,
    const float* __restrict__ bk, const float* __restrict__ gk,
    const float* __restrict__ betak, const float* __restrict__ Wb,
    const float* __restrict__ bb, float* __restrict__ beta)
{
    __shared__ float bks[HDIM], gks[HDIM], cqs[HDIM], wbs[HDIM];
    const int b    = blockIdx.x;
    const int tid  = threadIdx.x;
    const int lane = tid & 31;
    const int wid  = tid >> 5;

    for (int j = tid; j < HDIM; j += 256) {
        bks[j] = bk[j];
        gks[j] = gk[j];
        cqs[j] = betak[j] + q[(size_t)b * HDIM + j];
        wbs[j] = Wb[j];
    }
    __syncthreads();
    const float bbv = bb[0];

    for (int s = wid; s < SDIM; s += 8) {
        const size_t base = ((size_t)b * SDIM + s) * HDIM;
        float x[32];
        float sm = 0.f, sq = 0.f;
        #pragma unroll
        for (int it = 0; it < 4; it++) {
            int j0 = it * 256 + lane * 8;
            uint4 raw = *(const uint4*)(kc + base + j0);
            const __nv_bfloat162* v2 = (const __nv_bfloat162*)&raw;
            #pragma unroll
            for (int e = 0; e < 4; e++) {
                float a = __low2float(v2[e])  + bks[j0 + 2*e];
                float c = __high2float(v2[e]) + bks[j0 + 2*e + 1];
                x[it*8 + 2*e]     = a;
                x[it*8 + 2*e + 1] = c;
                sm += a + c; sq += a * a + c * c;
            }
        }
        #pragma unroll
        for (int o = 16; o > 0; o >>= 1) {
            sm += __shfl_xor_sync(0xffffffffu, sm, o);
            sq += __shfl_xor_sync(0xffffffffu, sq, o);
        }
        float mean = sm * (1.f / 1024.f);
        float var  = sq * (1.f / 1024.f) - mean * mean;
        float rstd = rsqrtf(var + 1e-5f);

        float acc = 0.f;
        #pragma unroll
        for (int it = 0; it < 4; it++) {
            int j0 = it * 256 + lane * 8;
            #pragma unroll
            for (int e = 0; e < 8; e++) {
                float hv = (x[it*8 + e] - mean) * rstd * gks[j0 + e] + cqs[j0 + e];
                acc += fmaxf(hv, 0.f) * wbs[j0 + e];
            }
        }
        #pragma unroll
        for (int o = 16; o > 0; o >>= 1)
            acc += __shfl_xor_sync(0xffffffffu, acc, o);

        if (lane == 0)
            beta[(size_t)b * SDIM + s] = (acc + bbv) * (1.f / 32.f);
    }
}

// ---------------- masked softmax + cumsums ----------------
__global__ void softmax_k(const float* __restrict__ beta,
                          const float* __restrict__ prev_p,
                          float* __restrict__ out)
{
    int b = blockIdx.x * blockDim.x + threadIdx.x;
    if (b >= BDIM) return;
    const float* bt = beta   + (size_t)b * SDIM;
    const float* pp = prev_p + (size_t)b * SDIM;

    float mx = -1e30f;
    #pragma unroll
    for (int s = 0; s < SDIM; s++) mx = fmaxf(mx, bt[s]);

    float pcs[SDIM];
    float run = 0.f;
    #pragma unroll
    for (int s = 0; s < SDIM; s++) { run += pp[s]; pcs[s] = run; }

    float x[SDIM];
    float denom = 0.f;
    #pragma unroll
    for (int s = 0; s < SDIM; s++) {
        float mask = (s < SDIM - 1)
                   ? ((pcs[s + 1] < 1e-5f) ? 0.f : pcs[s + 1])
                   : 1.f;
        x[s] = expf(bt[s] - mx) * mask;
        denom += fabsf(x[s]);
    }
    denom = fmaxf(denom, 1e-12f);

    const size_t BS = (size_t)BDIM * SDIM;
    float cp = 0.f;
    #pragma unroll
    for (int s = 0; s < SDIM; s++) {
        float p = x[s] / denom;
        x[s] = p;
        cp += p;
        out[0 * BS + (size_t)b * SDIM + s] = cp;
        out[2 * BS + (size_t)b * SDIM + s] = p;
    }
    float rcp = 0.f;
    #pragma unroll
    for (int s = SDIM - 1; s >= 0; s--) {
        rcp += x[s];
        out[1 * BS + (size_t)b * SDIM + s] = rcp;
    }
}

// ---------------- launch ----------------
extern "C" void kernel_launch(void* const* d_in, const int* in_sizes, int n_in,
                              void* d_out, int out_size)
{
    const float* in_val     = (const float*)d_in[0];
    const float* prev_out_M = (const float*)d_in[1];
    const float* prev_p     = (const float*)d_in[2];
    const float* Wq         = (const float*)d_in[3];
    const float* bq         = (const float*)d_in[4];
    const float* gq         = (const float*)d_in[5];
    const float* betaq      = (const float*)d_in[6];
    const float* Wk         = (const float*)d_in[7];
    const float* bk         = (const float*)d_in[8];
    const float* gk         = (const float*)d_in[9];
    const float* betak      = (const float*)d_in[10];
    const float* Wb         = (const float*)d_in[11];
    const float* bb         = (const float*)d_in[12];
    float* out = (float*)d_out;

    __nv_bfloat16 *wqt, *wkt, *kc, *qpre;
    float *qf, *betap;
    cudaGetSymbolAddress((void**)&wqt,   g_wqt);
    cudaGetSymbolAddress((void**)&wkt,   g_wkt);
    cudaGetSymbolAddress((void**)&kc,    g_kc);
    cudaGetSymbolAddress((void**)&qpre,  g_qpre);
    cudaGetSymbolAddress((void**)&qf,    g_q);
    cudaGetSymbolAddress((void**)&betap, g_beta);

    cudaFuncSetAttribute(gemm_bf16_k, cudaFuncAttributeMaxDynamicSharedMemorySize, GEMM_SMEM);

    cvtT_k<<<dim3(32, 32), dim3(32, 8)>>>(Wq, wqt);
    cvtT_k<<<dim3(32, 32), dim3(32, 8)>>>(Wk, wkt);

    gemm_bf16_k<<<dim3(8, BDIM  / 128), 256, GEMM_SMEM>>>(in_val,     wqt, qpre);
    gemm_bf16_k<<<dim3(8, MROWS / 128), 256, GEMM_SMEM>>>(prev_out_M, wkt, kc);

    ln_q_k   <<<BDIM / 8, 256>>>(qpre, bq, gq, betaq, qf);
    beta_k   <<<BDIM, 256>>>(kc, qf, bk, gk, betak, Wb, bb, betap);
    softmax_k<<<(BDIM + 127) / 128, 128>>>(betap, prev_p, out);
}